// round 12
// baseline (speedup 1.0000x reference)
#include <cuda_runtime.h>
#include <cuda_bf16.h>
#include <cstdint>

#define T_SEQ 4096
#define DM    1024
#define NH    16
#define HD    64

// Scratch (allocation-free: __device__ globals)
__device__ __nv_bfloat16 g_qhi[NH * T_SEQ * HD];
__device__ __nv_bfloat16 g_qlo[NH * T_SEQ * HD];
__device__ __nv_bfloat16 g_khi[NH * T_SEQ * HD];
__device__ __nv_bfloat16 g_klo[NH * T_SEQ * HD];
__device__ __nv_bfloat16 g_vhi[NH * T_SEQ * HD];
__device__ __nv_bfloat16 g_vlo[NH * T_SEQ * HD];
__device__ float g_ao[T_SEQ * DM];        // attention output, [T][D]

// ===========================================================================
// Helpers
// ===========================================================================
__device__ __forceinline__ uint32_t smem_to_u32(const void* p) {
    uint32_t a;
    asm("{ .reg .u64 t; cvta.to.shared.u64 t, %1; cvt.u32.u64 %0, t; }"
        : "=r"(a) : "l"(p));
    return a;
}

__device__ __forceinline__ void ldmatrix_x4(uint32_t* r, uint32_t addr) {
    asm volatile("ldmatrix.sync.aligned.m8n8.x4.shared.b16 {%0,%1,%2,%3}, [%4];"
                 : "=r"(r[0]), "=r"(r[1]), "=r"(r[2]), "=r"(r[3]) : "r"(addr));
}

__device__ __forceinline__ void ldmatrix_x4_trans(uint32_t* r, uint32_t addr) {
    asm volatile("ldmatrix.sync.aligned.m8n8.x4.trans.shared.b16 {%0,%1,%2,%3}, [%4];"
                 : "=r"(r[0]), "=r"(r[1]), "=r"(r[2]), "=r"(r[3]) : "r"(addr));
}

__device__ __forceinline__ void mma16816(float* c, const uint32_t* a,
                                         uint32_t b0, uint32_t b1) {
    asm volatile(
        "mma.sync.aligned.m16n8k16.row.col.f32.bf16.bf16.f32 "
        "{%0,%1,%2,%3}, {%4,%5,%6,%7}, {%8,%9}, {%0,%1,%2,%3};"
        : "+f"(c[0]), "+f"(c[1]), "+f"(c[2]), "+f"(c[3])
        : "r"(a[0]), "r"(a[1]), "r"(a[2]), "r"(a[3]), "r"(b0), "r"(b1));
}

__device__ __forceinline__ void cp_async16(uint32_t saddr, const void* gptr) {
    asm volatile("cp.async.cg.shared.global [%0], [%1], 16;"
                 :: "r"(saddr), "l"(gptr) : "memory");
}
#define CP_COMMIT() asm volatile("cp.async.commit_group;" ::: "memory")
#define CP_WAIT(n)  asm volatile("cp.async.wait_group %0;" :: "n"(n) : "memory")

__device__ __forceinline__ uint32_t packbf2(float x, float y) {
    __nv_bfloat162 h = __floats2bfloat162_rn(x, y);
    return *(uint32_t*)&h;
}

// (x, y) -> hi bf16x2 and residual-lo bf16x2
__device__ __forceinline__ void split2(float x, float y, uint32_t& h, uint32_t& l) {
    __nv_bfloat162 H = __floats2bfloat162_rn(x, y);
    __nv_bfloat162 L = __floats2bfloat162_rn(x - __bfloat162float(H.x),
                                             y - __bfloat162float(H.y));
    h = *(uint32_t*)&H; l = *(uint32_t*)&L;
}

__device__ __forceinline__ void split4(float4 v, uint32_t& h0, uint32_t& h1,
                                       uint32_t& l0, uint32_t& l1) {
    split2(v.x, v.y, h0, l0);
    split2(v.z, v.w, h1, l1);
}

__device__ __forceinline__ void sts2(uint32_t addr, uint32_t a, uint32_t b) {
    asm volatile("st.shared.v2.b32 [%0], {%1,%2};" :: "r"(addr), "r"(a), "r"(b) : "memory");
}

// ===========================================================================
// HMMA GEMM: C[M, N=1024] = X[M, K=1024] @ W[N, K]^T + bias[N]  (R6 mainloop)
// CTA 128x128, 8 warps (4m x 2n), warp tile 32x64, K chunk 32, stride 80 B.
// MODE 0: epilogue splits C into bf16 hi/lo, scattered head-major [h][t][64]
// MODE 1: plain fp32 row-major [m][n]
// ===========================================================================
template <int MODE>
__device__ __forceinline__ void gemm_mma_body(const float* __restrict__ X,
                                              const float* __restrict__ W,
                                              const float* __restrict__ bias,
                                              float* __restrict__ outf,
                                              __nv_bfloat16* __restrict__ ohi,
                                              __nv_bfloat16* __restrict__ olo) {
    __shared__ __nv_bfloat16 sAhi[128 * 40];
    __shared__ __nv_bfloat16 sAlo[128 * 40];
    __shared__ __nv_bfloat16 sBhi[128 * 40];
    __shared__ __nv_bfloat16 sBlo[128 * 40];

    const int tid = threadIdx.x;
    const int w = tid >> 5, lane = tid & 31;
    const int wm = w & 3, wn = w >> 2;
    const int bm = blockIdx.y * 128, bn = blockIdx.x * 128;

    const uint32_t uAhi = smem_to_u32(sAhi), uAlo = smem_to_u32(sAlo);
    const uint32_t uBhi = smem_to_u32(sBhi), uBlo = smem_to_u32(sBlo);

    const uint32_t mrow = lane & 15;
    const uint32_t mkb = (lane >> 4) * 16;

    const int grow = tid >> 3;
    const int gc4 = tid & 7;
    const float* Xp = X + (size_t)(bm + grow) * DM + gc4 * 4;
    const float* Wp = W + (size_t)(bn + grow) * DM + gc4 * 4;

    float c[2][8][4] = {};

    for (int k0 = 0; k0 < DM; k0 += 32) {
        float4 av[4], bv[4];
#pragma unroll
        for (int i = 0; i < 4; i++) {
            av[i] = *(const float4*)(Xp + k0 + (size_t)i * 32 * DM);
            bv[i] = *(const float4*)(Wp + k0 + (size_t)i * 32 * DM);
        }
        __syncthreads();
#pragma unroll
        for (int i = 0; i < 4; i++) {
            uint32_t byte = (uint32_t)(grow + 32 * i) * 80u + (uint32_t)gc4 * 8u;
            uint32_t h0, h1, l0, l1;
            split4(av[i], h0, h1, l0, l1);
            sts2(uAhi + byte, h0, h1);
            sts2(uAlo + byte, l0, l1);
            split4(bv[i], h0, h1, l0, l1);
            sts2(uBhi + byte, h0, h1);
            sts2(uBlo + byte, l0, l1);
        }
        __syncthreads();

#pragma unroll
        for (int ks = 0; ks < 2; ks++) {
            const uint32_t kbyte = (uint32_t)ks * 32u + mkb;
            uint32_t ah[2][4], al[2][4];
#pragma unroll
            for (int mt = 0; mt < 2; mt++) {
                uint32_t off = (uint32_t)(wm * 32 + mt * 16 + mrow) * 80u + kbyte;
                ldmatrix_x4(ah[mt], uAhi + off);
                ldmatrix_x4(al[mt], uAlo + off);
            }
#pragma unroll
            for (int np = 0; np < 4; np++) {
                uint32_t bh[4], bl[4];
                uint32_t off = (uint32_t)(wn * 64 + np * 16 + mrow) * 80u + kbyte;
                ldmatrix_x4(bh, uBhi + off);
                ldmatrix_x4(bl, uBlo + off);
#pragma unroll
                for (int mt = 0; mt < 2; mt++) {
                    float* c0 = c[mt][2 * np + 0];
                    float* c1 = c[mt][2 * np + 1];
                    mma16816(c0, ah[mt], bh[0], bh[2]);
                    mma16816(c1, ah[mt], bh[1], bh[3]);
                    mma16816(c0, ah[mt], bl[0], bl[2]);
                    mma16816(c1, ah[mt], bl[1], bl[3]);
                    mma16816(c0, al[mt], bh[0], bh[2]);
                    mma16816(c1, al[mt], bh[1], bh[3]);
                }
            }
        }
    }

    const int g = lane >> 2, tg = lane & 3;
#pragma unroll
    for (int mt = 0; mt < 2; mt++) {
#pragma unroll
        for (int j = 0; j < 8; j++) {
            int col = bn + wn * 64 + j * 8 + tg * 2;
            float bb0 = __ldg(bias + col), bb1 = __ldg(bias + col + 1);
            int r0 = bm + wm * 32 + mt * 16 + g;
            float cx0 = c[mt][j][0] + bb0, cy0 = c[mt][j][1] + bb1;
            float cx1 = c[mt][j][2] + bb0, cy1 = c[mt][j][3] + bb1;
            if (MODE == 0) {
                size_t basep = ((size_t)((col >> 6) * T_SEQ)) * HD + (col & 63);
                size_t i0 = basep + (size_t)r0 * HD;
                size_t i1 = basep + (size_t)(r0 + 8) * HD;
                uint32_t h, l;
                split2(cx0, cy0, h, l);
                *(uint32_t*)(ohi + i0) = h; *(uint32_t*)(olo + i0) = l;
                split2(cx1, cy1, h, l);
                *(uint32_t*)(ohi + i1) = h; *(uint32_t*)(olo + i1) = l;
            } else {
                *(float2*)(outf + (size_t)r0 * DM + col) = make_float2(cx0, cy0);
                *(float2*)(outf + (size_t)(r0 + 8) * DM + col) = make_float2(cx1, cy1);
            }
        }
    }
}

__global__ void __launch_bounds__(256, 2) gemm_mma_proj(const float* __restrict__ X,
                                                        const float* __restrict__ W,
                                                        const float* __restrict__ bias,
                                                        int which) {
    __nv_bfloat16* ohi = (which == 0) ? g_qhi : (which == 1) ? g_khi : g_vhi;
    __nv_bfloat16* olo = (which == 0) ? g_qlo : (which == 1) ? g_klo : g_vlo;
    gemm_mma_body<0>(X, W, bias, nullptr, ohi, olo);
}

__global__ void __launch_bounds__(256, 2) gemm_mma_out(const float* __restrict__ W,
                                                       const float* __restrict__ bias,
                                                       float* __restrict__ out) {
    gemm_mma_body<1>(g_ao, W, bias, out, nullptr, nullptr);
}

// ===========================================================================
// HMMA flash attention (causal). Block = (64-query tile, head), 4 warps.
// R9: K/V/Q arrive PRE-SPLIT as bf16 hi/lo; cp.async loads them straight into
// ldmatrix-ready smem (144 B row stride). No conversion in the loop. Double-
// buffered: 2 stages x (Khi|Klo|Vhi|Vlo) x 9216 B = 72 KB -> 3 CTAs/SM.
// ===========================================================================
#define AST   72                      // bf16 row stride (144 B)
#define AREG  (64 * AST * 2)          // one array region: 9216 B
#define ASTAGE (4 * AREG)             // one stage: 36864 B
#define ATT_SMEM (2 * ASTAGE)         // 73728 B

__global__ void __launch_bounds__(128) flash_attn_mma() {
    extern __shared__ char dsm[];
    const uint32_t base = smem_to_u32(dsm);

    const int tid = threadIdx.x;
    const int w = tid >> 5, lane = tid & 31;
    const int g = lane >> 2, tg = lane & 3;
    const uint32_t mrow = lane & 15;
    const uint32_t mkb = (lane >> 4) * 16;
    const int qt = (int)gridDim.x - 1 - (int)blockIdx.x;   // big tiles first
    const int h = blockIdx.y;
    const int q0 = qt * 64;

    // cp.async mapping: per array 512 16B-chunks; 128 threads x 4 chunks
    // chunk c = tid + 128*i -> row = c>>3, ch = c&7
    const __nv_bfloat16* Khi0 = g_khi + (size_t)h * T_SEQ * HD;
    const __nv_bfloat16* Klo0 = g_klo + (size_t)h * T_SEQ * HD;
    const __nv_bfloat16* Vhi0 = g_vhi + (size_t)h * T_SEQ * HD;
    const __nv_bfloat16* Vlo0 = g_vlo + (size_t)h * T_SEQ * HD;

    // ---- prologue: Q (into stage1 K region) + key tile 0 (stage0), 1 group
    {
        const __nv_bfloat16* Qhi = g_qhi + ((size_t)h * T_SEQ + q0) * HD;
        const __nv_bfloat16* Qlo = g_qlo + ((size_t)h * T_SEQ + q0) * HD;
#pragma unroll
        for (int i = 0; i < 4; i++) {
            int c = tid + 128 * i;
            int row = c >> 3, ch = c & 7;
            uint32_t dst = (uint32_t)row * (AST * 2u) + (uint32_t)ch * 16u;
            size_t src = (size_t)row * HD + ch * 8;
            cp_async16(base + ASTAGE + dst,            Qhi + src);   // stage1 Khi
            cp_async16(base + ASTAGE + AREG + dst,     Qlo + src);   // stage1 Klo
            cp_async16(base + dst,                     Khi0 + src);  // stage0
            cp_async16(base + AREG + dst,              Klo0 + src);
            cp_async16(base + 2 * AREG + dst,          Vhi0 + src);
            cp_async16(base + 3 * AREG + dst,          Vlo0 + src);
        }
        CP_COMMIT();
        CP_WAIT(0);
    }
    __syncthreads();

    // ---- hoist Q fragments from stage1 K region ----
    uint32_t qh[4][4], ql[4][4];
#pragma unroll
    for (int kc = 0; kc < 4; kc++) {
        uint32_t off = (uint32_t)(w * 16 + mrow) * (AST * 2u) + (uint32_t)kc * 32u + mkb;
        ldmatrix_x4(qh[kc], base + ASTAGE + off);
        ldmatrix_x4(ql[kc], base + ASTAGE + AREG + off);
    }

    float O[8][4] = {};
    float m0 = -1e30f, m1 = -1e30f, l0s = 0.f, l1s = 0.f;

    for (int kt = 0; kt <= qt; kt++) {
        __syncthreads();   // prior compute (or Q hoist) done before overwrite
        if (kt < qt) {
            const uint32_t sb = (uint32_t)((kt + 1) & 1) * ASTAGE;
            const size_t t0 = (size_t)(kt + 1) * 64 * HD;
#pragma unroll
            for (int i = 0; i < 4; i++) {
                int c = tid + 128 * i;
                int row = c >> 3, ch = c & 7;
                uint32_t dst = sb + (uint32_t)row * (AST * 2u) + (uint32_t)ch * 16u;
                size_t src = t0 + (size_t)row * HD + ch * 8;
                cp_async16(base + dst,            Khi0 + src);
                cp_async16(base + AREG + dst,     Klo0 + src);
                cp_async16(base + 2 * AREG + dst, Vhi0 + src);
                cp_async16(base + 3 * AREG + dst, Vlo0 + src);
            }
            CP_COMMIT();
            CP_WAIT(1);
        } else {
            CP_WAIT(0);
        }
        __syncthreads();

        const uint32_t uKhi = base + (uint32_t)(kt & 1) * ASTAGE;
        const uint32_t uKlo = uKhi + AREG;
        const uint32_t uVhi = uKhi + 2 * AREG;
        const uint32_t uVlo = uKhi + 3 * AREG;

        // ---- S = Q @ K^T (c[j] = 8-col key tile j) ----
        float c[8][4] = {};
#pragma unroll
        for (int kc = 0; kc < 4; kc++) {
#pragma unroll
            for (int np = 0; np < 4; np++) {
                uint32_t kh[4], kl[4];
                uint32_t off = (uint32_t)(np * 16 + mrow) * (AST * 2u) + (uint32_t)kc * 32u + mkb;
                ldmatrix_x4(kh, uKhi + off);
                ldmatrix_x4(kl, uKlo + off);
                float* c0 = c[2 * np + 0];
                float* c1 = c[2 * np + 1];
                mma16816(c0, qh[kc], kh[0], kh[2]);
                mma16816(c1, qh[kc], kh[1], kh[3]);
                mma16816(c0, qh[kc], kl[0], kl[2]);
                mma16816(c1, qh[kc], kl[1], kl[3]);
                mma16816(c0, ql[kc], kh[0], kh[2]);
                mma16816(c1, ql[kc], kh[1], kh[3]);
            }
        }

        // ---- scale + causal mask (diag tile only) ----
        const float scale = 0.125f;
        if (kt == qt) {
            const int r0 = 16 * w + g, r1 = r0 + 8;
#pragma unroll
            for (int j = 0; j < 8; j++) {
                int col = 8 * j + 2 * tg;
                c[j][0] = (col     <= r0) ? c[j][0] * scale : -1e30f;
                c[j][1] = (col + 1 <= r0) ? c[j][1] * scale : -1e30f;
                c[j][2] = (col     <= r1) ? c[j][2] * scale : -1e30f;
                c[j][3] = (col + 1 <= r1) ? c[j][3] * scale : -1e30f;
            }
        } else {
#pragma unroll
            for (int j = 0; j < 8; j++)
#pragma unroll
                for (int q = 0; q < 4; q++) c[j][q] *= scale;
        }

        // ---- online softmax (rows g and g+8; reduce over 4-lane group) ----
        float rm0 = -1e30f, rm1 = -1e30f;
#pragma unroll
        for (int j = 0; j < 8; j++) {
            rm0 = fmaxf(rm0, fmaxf(c[j][0], c[j][1]));
            rm1 = fmaxf(rm1, fmaxf(c[j][2], c[j][3]));
        }
        rm0 = fmaxf(rm0, __shfl_xor_sync(0xffffffffu, rm0, 1));
        rm0 = fmaxf(rm0, __shfl_xor_sync(0xffffffffu, rm0, 2));
        rm1 = fmaxf(rm1, __shfl_xor_sync(0xffffffffu, rm1, 1));
        rm1 = fmaxf(rm1, __shfl_xor_sync(0xffffffffu, rm1, 2));

        float mn0 = fmaxf(m0, rm0), mn1 = fmaxf(m1, rm1);
        float a0 = __expf(m0 - mn0), a1 = __expf(m1 - mn1);
        m0 = mn0; m1 = mn1;

        float rs0 = 0.f, rs1 = 0.f;
#pragma unroll
        for (int j = 0; j < 8; j++) {
            c[j][0] = __expf(c[j][0] - mn0);
            c[j][1] = __expf(c[j][1] - mn0);
            c[j][2] = __expf(c[j][2] - mn1);
            c[j][3] = __expf(c[j][3] - mn1);
            rs0 += c[j][0] + c[j][1];
            rs1 += c[j][2] + c[j][3];
        }
        rs0 += __shfl_xor_sync(0xffffffffu, rs0, 1);
        rs0 += __shfl_xor_sync(0xffffffffu, rs0, 2);
        rs1 += __shfl_xor_sync(0xffffffffu, rs1, 1);
        rs1 += __shfl_xor_sync(0xffffffffu, rs1, 2);
        l0s = l0s * a0 + rs0;
        l1s = l1s * a1 + rs1;
#pragma unroll
        for (int j = 0; j < 8; j++) {
            O[j][0] *= a0; O[j][1] *= a0;
            O[j][2] *= a1; O[j][3] *= a1;
        }

        // ---- O += P @ V  (P fragments straight from c; V via ldmatrix.trans)
#pragma unroll
        for (int kc = 0; kc < 4; kc++) {
            const int j0 = 2 * kc, j1 = 2 * kc + 1;
            uint32_t ph[4], pl[4];
            {
                uint32_t hh, ll;
                split2(c[j0][0], c[j0][1], hh, ll); ph[0] = hh; pl[0] = ll;
                split2(c[j0][2], c[j0][3], hh, ll); ph[1] = hh; pl[1] = ll;
                split2(c[j1][0], c[j1][1], hh, ll); ph[2] = hh; pl[2] = ll;
                split2(c[j1][2], c[j1][3], hh, ll); ph[3] = hh; pl[3] = ll;
            }
#pragma unroll
            for (int dt = 0; dt < 4; dt++) {
                uint32_t vh[4], vl[4];
                uint32_t off = (uint32_t)(kc * 16 + mrow) * (AST * 2u) + (uint32_t)dt * 32u + mkb;
                ldmatrix_x4_trans(vh, uVhi + off);
                ldmatrix_x4_trans(vl, uVlo + off);
                float* o0 = O[2 * dt + 0];
                float* o1 = O[2 * dt + 1];
                mma16816(o0, ph, vh[0], vh[1]);
                mma16816(o1, ph, vh[2], vh[3]);
                mma16816(o0, ph, vl[0], vl[1]);
                mma16816(o1, ph, vl[2], vl[3]);
                mma16816(o0, pl, vh[0], vh[1]);
                mma16816(o1, pl, vh[2], vh[3]);
            }
        }
    }

    // ---- epilogue: O / l -> g_ao[t][h*64 + d] ----
    const float inv0 = 1.0f / l0s, inv1 = 1.0f / l1s;
    const int r0 = q0 + 16 * w + g, r1 = r0 + 8;
#pragma unroll
    for (int j = 0; j < 8; j++) {
        int d = 8 * j + 2 * tg;
        float2 v0 = {O[j][0] * inv0, O[j][1] * inv0};
        float2 v1 = {O[j][2] * inv1, O[j][3] * inv1};
        *(float2*)(g_ao + (size_t)r0 * DM + h * HD + d) = v0;
        *(float2*)(g_ao + (size_t)r1 * DM + h * HD + d) = v1;
    }
}

// ---------------------------------------------------------------------------
extern "C" void kernel_launch(void* const* d_in, const int* in_sizes, int n_in,
                              void* d_out, int out_size) {
    const float* q   = (const float*)d_in[0];
    const float* k   = (const float*)d_in[1];
    const float* v   = (const float*)d_in[2];
    // d_in[3] = causal mask (bool) — implied by causal structure, unused
    const float* w_q = (const float*)d_in[4];
    const float* b_q = (const float*)d_in[5];
    const float* w_k = (const float*)d_in[6];
    const float* b_k = (const float*)d_in[7];
    const float* w_v = (const float*)d_in[8];
    const float* b_v = (const float*)d_in[9];
    const float* w_o = (const float*)d_in[10];
    const float* b_o = (const float*)d_in[11];
    float* out = (float*)d_out;

    cudaFuncSetAttribute(flash_attn_mma, cudaFuncAttributeMaxDynamicSharedMemorySize, ATT_SMEM);

    dim3 gg(DM / 128, T_SEQ / 128);   // (8, 32)
    gemm_mma_proj<<<gg, 256>>>(q, w_q, b_q, 0);
    gemm_mma_proj<<<gg, 256>>>(k, w_k, b_k, 1);
    gemm_mma_proj<<<gg, 256>>>(v, w_v, b_v, 2);
    flash_attn_mma<<<dim3(T_SEQ / 64, NH), 128, ATT_SMEM>>>();
    gemm_mma_out<<<gg, 256>>>(w_o, b_o, out);
}

// round 13
// speedup vs baseline: 1.0000x; 1.0000x over previous
#include <cuda_runtime.h>
#include <cuda_bf16.h>
#include <cstdint>

#define T_SEQ 4096
#define DM    1024
#define NH    16
#define HD    64

// Scratch (allocation-free: __device__ globals)
__device__ __nv_bfloat16 g_qhi[NH * T_SEQ * HD];
__device__ __nv_bfloat16 g_qlo[NH * T_SEQ * HD];
__device__ __nv_bfloat16 g_khi[NH * T_SEQ * HD];
__device__ __nv_bfloat16 g_klo[NH * T_SEQ * HD];
__device__ __nv_bfloat16 g_vhi[NH * T_SEQ * HD];
__device__ __nv_bfloat16 g_vlo[NH * T_SEQ * HD];
__device__ float g_ao[T_SEQ * DM];        // attention output, [T][D]

// ===========================================================================
// Helpers
// ===========================================================================
__device__ __forceinline__ uint32_t smem_to_u32(const void* p) {
    uint32_t a;
    asm("{ .reg .u64 t; cvta.to.shared.u64 t, %1; cvt.u32.u64 %0, t; }"
        : "=r"(a) : "l"(p));
    return a;
}

__device__ __forceinline__ void ldmatrix_x4(uint32_t* r, uint32_t addr) {
    asm volatile("ldmatrix.sync.aligned.m8n8.x4.shared.b16 {%0,%1,%2,%3}, [%4];"
                 : "=r"(r[0]), "=r"(r[1]), "=r"(r[2]), "=r"(r[3]) : "r"(addr));
}

__device__ __forceinline__ void ldmatrix_x4_trans(uint32_t* r, uint32_t addr) {
    asm volatile("ldmatrix.sync.aligned.m8n8.x4.trans.shared.b16 {%0,%1,%2,%3}, [%4];"
                 : "=r"(r[0]), "=r"(r[1]), "=r"(r[2]), "=r"(r[3]) : "r"(addr));
}

__device__ __forceinline__ void mma16816(float* c, const uint32_t* a,
                                         uint32_t b0, uint32_t b1) {
    asm volatile(
        "mma.sync.aligned.m16n8k16.row.col.f32.bf16.bf16.f32 "
        "{%0,%1,%2,%3}, {%4,%5,%6,%7}, {%8,%9}, {%0,%1,%2,%3};"
        : "+f"(c[0]), "+f"(c[1]), "+f"(c[2]), "+f"(c[3])
        : "r"(a[0]), "r"(a[1]), "r"(a[2]), "r"(a[3]), "r"(b0), "r"(b1));
}

__device__ __forceinline__ void cp_async16(uint32_t saddr, const void* gptr) {
    asm volatile("cp.async.cg.shared.global [%0], [%1], 16;"
                 :: "r"(saddr), "l"(gptr) : "memory");
}
#define CP_COMMIT() asm volatile("cp.async.commit_group;" ::: "memory")
#define CP_WAIT(n)  asm volatile("cp.async.wait_group %0;" :: "n"(n) : "memory")

__device__ __forceinline__ uint32_t packbf2(float x, float y) {
    __nv_bfloat162 h = __floats2bfloat162_rn(x, y);
    return *(uint32_t*)&h;
}

// (x, y) -> hi bf16x2 and residual-lo bf16x2
__device__ __forceinline__ void split2(float x, float y, uint32_t& h, uint32_t& l) {
    __nv_bfloat162 H = __floats2bfloat162_rn(x, y);
    __nv_bfloat162 L = __floats2bfloat162_rn(x - __bfloat162float(H.x),
                                             y - __bfloat162float(H.y));
    h = *(uint32_t*)&H; l = *(uint32_t*)&L;
}

__device__ __forceinline__ void split4(float4 v, uint32_t& h0, uint32_t& h1,
                                       uint32_t& l0, uint32_t& l1) {
    split2(v.x, v.y, h0, l0);
    split2(v.z, v.w, h1, l1);
}

__device__ __forceinline__ void sts2(uint32_t addr, uint32_t a, uint32_t b) {
    asm volatile("st.shared.v2.b32 [%0], {%1,%2};" :: "r"(addr), "r"(a), "r"(b) : "memory");
}

// ===========================================================================
// HMMA GEMM: C[M, N=1024] = X[M, K=1024] @ W[N, K]^T + bias[N]  (R6 mainloop)
// CTA 128x128, 8 warps (4m x 2n), warp tile 32x64, K chunk 32, stride 80 B.
// MODE 0: epilogue splits C into bf16 hi/lo, scattered head-major [h][t][64]
// MODE 1: plain fp32 row-major [m][n]
// ===========================================================================
template <int MODE>
__device__ __forceinline__ void gemm_mma_body(const float* __restrict__ X,
                                              const float* __restrict__ W,
                                              const float* __restrict__ bias,
                                              float* __restrict__ outf,
                                              __nv_bfloat16* __restrict__ ohi,
                                              __nv_bfloat16* __restrict__ olo) {
    __shared__ __nv_bfloat16 sAhi[128 * 40];
    __shared__ __nv_bfloat16 sAlo[128 * 40];
    __shared__ __nv_bfloat16 sBhi[128 * 40];
    __shared__ __nv_bfloat16 sBlo[128 * 40];

    const int tid = threadIdx.x;
    const int w = tid >> 5, lane = tid & 31;
    const int wm = w & 3, wn = w >> 2;
    const int bm = blockIdx.y * 128, bn = blockIdx.x * 128;

    const uint32_t uAhi = smem_to_u32(sAhi), uAlo = smem_to_u32(sAlo);
    const uint32_t uBhi = smem_to_u32(sBhi), uBlo = smem_to_u32(sBlo);

    const uint32_t mrow = lane & 15;
    const uint32_t mkb = (lane >> 4) * 16;

    const int grow = tid >> 3;
    const int gc4 = tid & 7;
    const float* Xp = X + (size_t)(bm + grow) * DM + gc4 * 4;
    const float* Wp = W + (size_t)(bn + grow) * DM + gc4 * 4;

    float c[2][8][4] = {};

    for (int k0 = 0; k0 < DM; k0 += 32) {
        float4 av[4], bv[4];
#pragma unroll
        for (int i = 0; i < 4; i++) {
            av[i] = *(const float4*)(Xp + k0 + (size_t)i * 32 * DM);
            bv[i] = *(const float4*)(Wp + k0 + (size_t)i * 32 * DM);
        }
        __syncthreads();
#pragma unroll
        for (int i = 0; i < 4; i++) {
            uint32_t byte = (uint32_t)(grow + 32 * i) * 80u + (uint32_t)gc4 * 8u;
            uint32_t h0, h1, l0, l1;
            split4(av[i], h0, h1, l0, l1);
            sts2(uAhi + byte, h0, h1);
            sts2(uAlo + byte, l0, l1);
            split4(bv[i], h0, h1, l0, l1);
            sts2(uBhi + byte, h0, h1);
            sts2(uBlo + byte, l0, l1);
        }
        __syncthreads();

#pragma unroll
        for (int ks = 0; ks < 2; ks++) {
            const uint32_t kbyte = (uint32_t)ks * 32u + mkb;
            uint32_t ah[2][4], al[2][4];
#pragma unroll
            for (int mt = 0; mt < 2; mt++) {
                uint32_t off = (uint32_t)(wm * 32 + mt * 16 + mrow) * 80u + kbyte;
                ldmatrix_x4(ah[mt], uAhi + off);
                ldmatrix_x4(al[mt], uAlo + off);
            }
#pragma unroll
            for (int np = 0; np < 4; np++) {
                uint32_t bh[4], bl[4];
                uint32_t off = (uint32_t)(wn * 64 + np * 16 + mrow) * 80u + kbyte;
                ldmatrix_x4(bh, uBhi + off);
                ldmatrix_x4(bl, uBlo + off);
#pragma unroll
                for (int mt = 0; mt < 2; mt++) {
                    float* c0 = c[mt][2 * np + 0];
                    float* c1 = c[mt][2 * np + 1];
                    mma16816(c0, ah[mt], bh[0], bh[2]);
                    mma16816(c1, ah[mt], bh[1], bh[3]);
                    mma16816(c0, ah[mt], bl[0], bl[2]);
                    mma16816(c1, ah[mt], bl[1], bl[3]);
                    mma16816(c0, al[mt], bh[0], bh[2]);
                    mma16816(c1, al[mt], bh[1], bh[3]);
                }
            }
        }
    }

    const int g = lane >> 2, tg = lane & 3;
#pragma unroll
    for (int mt = 0; mt < 2; mt++) {
#pragma unroll
        for (int j = 0; j < 8; j++) {
            int col = bn + wn * 64 + j * 8 + tg * 2;
            float bb0 = __ldg(bias + col), bb1 = __ldg(bias + col + 1);
            int r0 = bm + wm * 32 + mt * 16 + g;
            float cx0 = c[mt][j][0] + bb0, cy0 = c[mt][j][1] + bb1;
            float cx1 = c[mt][j][2] + bb0, cy1 = c[mt][j][3] + bb1;
            if (MODE == 0) {
                size_t basep = ((size_t)((col >> 6) * T_SEQ)) * HD + (col & 63);
                size_t i0 = basep + (size_t)r0 * HD;
                size_t i1 = basep + (size_t)(r0 + 8) * HD;
                uint32_t h, l;
                split2(cx0, cy0, h, l);
                *(uint32_t*)(ohi + i0) = h; *(uint32_t*)(olo + i0) = l;
                split2(cx1, cy1, h, l);
                *(uint32_t*)(ohi + i1) = h; *(uint32_t*)(olo + i1) = l;
            } else {
                *(float2*)(outf + (size_t)r0 * DM + col) = make_float2(cx0, cy0);
                *(float2*)(outf + (size_t)(r0 + 8) * DM + col) = make_float2(cx1, cy1);
            }
        }
    }
}

__global__ void __launch_bounds__(256, 2) gemm_mma_proj(const float* __restrict__ X,
                                                        const float* __restrict__ W,
                                                        const float* __restrict__ bias,
                                                        int which) {
    __nv_bfloat16* ohi = (which == 0) ? g_qhi : (which == 1) ? g_khi : g_vhi;
    __nv_bfloat16* olo = (which == 0) ? g_qlo : (which == 1) ? g_klo : g_vlo;
    gemm_mma_body<0>(X, W, bias, nullptr, ohi, olo);
}

__global__ void __launch_bounds__(256, 2) gemm_mma_out(const float* __restrict__ W,
                                                       const float* __restrict__ bias,
                                                       float* __restrict__ out) {
    gemm_mma_body<1>(g_ao, W, bias, out, nullptr, nullptr);
}

// ===========================================================================
// HMMA flash attention (causal). Block = (64-query tile, head), 4 warps.
// R9: K/V/Q arrive PRE-SPLIT as bf16 hi/lo; cp.async loads them straight into
// ldmatrix-ready smem (144 B row stride). No conversion in the loop. Double-
// buffered: 2 stages x (Khi|Klo|Vhi|Vlo) x 9216 B = 72 KB -> 3 CTAs/SM.
// ===========================================================================
#define AST   72                      // bf16 row stride (144 B)
#define AREG  (64 * AST * 2)          // one array region: 9216 B
#define ASTAGE (4 * AREG)             // one stage: 36864 B
#define ATT_SMEM (2 * ASTAGE)         // 73728 B

__global__ void __launch_bounds__(128) flash_attn_mma() {
    extern __shared__ char dsm[];
    const uint32_t base = smem_to_u32(dsm);

    const int tid = threadIdx.x;
    const int w = tid >> 5, lane = tid & 31;
    const int g = lane >> 2, tg = lane & 3;
    const uint32_t mrow = lane & 15;
    const uint32_t mkb = (lane >> 4) * 16;
    const int qt = (int)gridDim.x - 1 - (int)blockIdx.x;   // big tiles first
    const int h = blockIdx.y;
    const int q0 = qt * 64;

    // cp.async mapping: per array 512 16B-chunks; 128 threads x 4 chunks
    // chunk c = tid + 128*i -> row = c>>3, ch = c&7
    const __nv_bfloat16* Khi0 = g_khi + (size_t)h * T_SEQ * HD;
    const __nv_bfloat16* Klo0 = g_klo + (size_t)h * T_SEQ * HD;
    const __nv_bfloat16* Vhi0 = g_vhi + (size_t)h * T_SEQ * HD;
    const __nv_bfloat16* Vlo0 = g_vlo + (size_t)h * T_SEQ * HD;

    // ---- prologue: Q (into stage1 K region) + key tile 0 (stage0), 1 group
    {
        const __nv_bfloat16* Qhi = g_qhi + ((size_t)h * T_SEQ + q0) * HD;
        const __nv_bfloat16* Qlo = g_qlo + ((size_t)h * T_SEQ + q0) * HD;
#pragma unroll
        for (int i = 0; i < 4; i++) {
            int c = tid + 128 * i;
            int row = c >> 3, ch = c & 7;
            uint32_t dst = (uint32_t)row * (AST * 2u) + (uint32_t)ch * 16u;
            size_t src = (size_t)row * HD + ch * 8;
            cp_async16(base + ASTAGE + dst,            Qhi + src);   // stage1 Khi
            cp_async16(base + ASTAGE + AREG + dst,     Qlo + src);   // stage1 Klo
            cp_async16(base + dst,                     Khi0 + src);  // stage0
            cp_async16(base + AREG + dst,              Klo0 + src);
            cp_async16(base + 2 * AREG + dst,          Vhi0 + src);
            cp_async16(base + 3 * AREG + dst,          Vlo0 + src);
        }
        CP_COMMIT();
        CP_WAIT(0);
    }
    __syncthreads();

    // ---- hoist Q fragments from stage1 K region ----
    uint32_t qh[4][4], ql[4][4];
#pragma unroll
    for (int kc = 0; kc < 4; kc++) {
        uint32_t off = (uint32_t)(w * 16 + mrow) * (AST * 2u) + (uint32_t)kc * 32u + mkb;
        ldmatrix_x4(qh[kc], base + ASTAGE + off);
        ldmatrix_x4(ql[kc], base + ASTAGE + AREG + off);
    }

    float O[8][4] = {};
    float m0 = -1e30f, m1 = -1e30f, l0s = 0.f, l1s = 0.f;

    for (int kt = 0; kt <= qt; kt++) {
        __syncthreads();   // prior compute (or Q hoist) done before overwrite
        if (kt < qt) {
            const uint32_t sb = (uint32_t)((kt + 1) & 1) * ASTAGE;
            const size_t t0 = (size_t)(kt + 1) * 64 * HD;
#pragma unroll
            for (int i = 0; i < 4; i++) {
                int c = tid + 128 * i;
                int row = c >> 3, ch = c & 7;
                uint32_t dst = sb + (uint32_t)row * (AST * 2u) + (uint32_t)ch * 16u;
                size_t src = t0 + (size_t)row * HD + ch * 8;
                cp_async16(base + dst,            Khi0 + src);
                cp_async16(base + AREG + dst,     Klo0 + src);
                cp_async16(base + 2 * AREG + dst, Vhi0 + src);
                cp_async16(base + 3 * AREG + dst, Vlo0 + src);
            }
            CP_COMMIT();
            CP_WAIT(1);
        } else {
            CP_WAIT(0);
        }
        __syncthreads();

        const uint32_t uKhi = base + (uint32_t)(kt & 1) * ASTAGE;
        const uint32_t uKlo = uKhi + AREG;
        const uint32_t uVhi = uKhi + 2 * AREG;
        const uint32_t uVlo = uKhi + 3 * AREG;

        // ---- S = Q @ K^T (c[j] = 8-col key tile j) ----
        float c[8][4] = {};
#pragma unroll
        for (int kc = 0; kc < 4; kc++) {
#pragma unroll
            for (int np = 0; np < 4; np++) {
                uint32_t kh[4], kl[4];
                uint32_t off = (uint32_t)(np * 16 + mrow) * (AST * 2u) + (uint32_t)kc * 32u + mkb;
                ldmatrix_x4(kh, uKhi + off);
                ldmatrix_x4(kl, uKlo + off);
                float* c0 = c[2 * np + 0];
                float* c1 = c[2 * np + 1];
                mma16816(c0, qh[kc], kh[0], kh[2]);
                mma16816(c1, qh[kc], kh[1], kh[3]);
                mma16816(c0, qh[kc], kl[0], kl[2]);
                mma16816(c1, qh[kc], kl[1], kl[3]);
                mma16816(c0, ql[kc], kh[0], kh[2]);
                mma16816(c1, ql[kc], kh[1], kh[3]);
            }
        }

        // ---- scale + causal mask (diag tile only) ----
        const float scale = 0.125f;
        if (kt == qt) {
            const int r0 = 16 * w + g, r1 = r0 + 8;
#pragma unroll
            for (int j = 0; j < 8; j++) {
                int col = 8 * j + 2 * tg;
                c[j][0] = (col     <= r0) ? c[j][0] * scale : -1e30f;
                c[j][1] = (col + 1 <= r0) ? c[j][1] * scale : -1e30f;
                c[j][2] = (col     <= r1) ? c[j][2] * scale : -1e30f;
                c[j][3] = (col + 1 <= r1) ? c[j][3] * scale : -1e30f;
            }
        } else {
#pragma unroll
            for (int j = 0; j < 8; j++)
#pragma unroll
                for (int q = 0; q < 4; q++) c[j][q] *= scale;
        }

        // ---- online softmax (rows g and g+8; reduce over 4-lane group) ----
        float rm0 = -1e30f, rm1 = -1e30f;
#pragma unroll
        for (int j = 0; j < 8; j++) {
            rm0 = fmaxf(rm0, fmaxf(c[j][0], c[j][1]));
            rm1 = fmaxf(rm1, fmaxf(c[j][2], c[j][3]));
        }
        rm0 = fmaxf(rm0, __shfl_xor_sync(0xffffffffu, rm0, 1));
        rm0 = fmaxf(rm0, __shfl_xor_sync(0xffffffffu, rm0, 2));
        rm1 = fmaxf(rm1, __shfl_xor_sync(0xffffffffu, rm1, 1));
        rm1 = fmaxf(rm1, __shfl_xor_sync(0xffffffffu, rm1, 2));

        float mn0 = fmaxf(m0, rm0), mn1 = fmaxf(m1, rm1);
        float a0 = __expf(m0 - mn0), a1 = __expf(m1 - mn1);
        m0 = mn0; m1 = mn1;

        float rs0 = 0.f, rs1 = 0.f;
#pragma unroll
        for (int j = 0; j < 8; j++) {
            c[j][0] = __expf(c[j][0] - mn0);
            c[j][1] = __expf(c[j][1] - mn0);
            c[j][2] = __expf(c[j][2] - mn1);
            c[j][3] = __expf(c[j][3] - mn1);
            rs0 += c[j][0] + c[j][1];
            rs1 += c[j][2] + c[j][3];
        }
        rs0 += __shfl_xor_sync(0xffffffffu, rs0, 1);
        rs0 += __shfl_xor_sync(0xffffffffu, rs0, 2);
        rs1 += __shfl_xor_sync(0xffffffffu, rs1, 1);
        rs1 += __shfl_xor_sync(0xffffffffu, rs1, 2);
        l0s = l0s * a0 + rs0;
        l1s = l1s * a1 + rs1;
#pragma unroll
        for (int j = 0; j < 8; j++) {
            O[j][0] *= a0; O[j][1] *= a0;
            O[j][2] *= a1; O[j][3] *= a1;
        }

        // ---- O += P @ V  (P fragments straight from c; V via ldmatrix.trans)
#pragma unroll
        for (int kc = 0; kc < 4; kc++) {
            const int j0 = 2 * kc, j1 = 2 * kc + 1;
            uint32_t ph[4], pl[4];
            {
                uint32_t hh, ll;
                split2(c[j0][0], c[j0][1], hh, ll); ph[0] = hh; pl[0] = ll;
                split2(c[j0][2], c[j0][3], hh, ll); ph[1] = hh; pl[1] = ll;
                split2(c[j1][0], c[j1][1], hh, ll); ph[2] = hh; pl[2] = ll;
                split2(c[j1][2], c[j1][3], hh, ll); ph[3] = hh; pl[3] = ll;
            }
#pragma unroll
            for (int dt = 0; dt < 4; dt++) {
                uint32_t vh[4], vl[4];
                uint32_t off = (uint32_t)(kc * 16 + mrow) * (AST * 2u) + (uint32_t)dt * 32u + mkb;
                ldmatrix_x4_trans(vh, uVhi + off);
                ldmatrix_x4_trans(vl, uVlo + off);
                float* o0 = O[2 * dt + 0];
                float* o1 = O[2 * dt + 1];
                mma16816(o0, ph, vh[0], vh[1]);
                mma16816(o1, ph, vh[2], vh[3]);
                mma16816(o0, ph, vl[0], vl[1]);
                mma16816(o1, ph, vl[2], vl[3]);
                mma16816(o0, pl, vh[0], vh[1]);
                mma16816(o1, pl, vh[2], vh[3]);
            }
        }
    }

    // ---- epilogue: O / l -> g_ao[t][h*64 + d] ----
    const float inv0 = 1.0f / l0s, inv1 = 1.0f / l1s;
    const int r0 = q0 + 16 * w + g, r1 = r0 + 8;
#pragma unroll
    for (int j = 0; j < 8; j++) {
        int d = 8 * j + 2 * tg;
        float2 v0 = {O[j][0] * inv0, O[j][1] * inv0};
        float2 v1 = {O[j][2] * inv1, O[j][3] * inv1};
        *(float2*)(g_ao + (size_t)r0 * DM + h * HD + d) = v0;
        *(float2*)(g_ao + (size_t)r1 * DM + h * HD + d) = v1;
    }
}

// ---------------------------------------------------------------------------
extern "C" void kernel_launch(void* const* d_in, const int* in_sizes, int n_in,
                              void* d_out, int out_size) {
    const float* q   = (const float*)d_in[0];
    const float* k   = (const float*)d_in[1];
    const float* v   = (const float*)d_in[2];
    // d_in[3] = causal mask (bool) — implied by causal structure, unused
    const float* w_q = (const float*)d_in[4];
    const float* b_q = (const float*)d_in[5];
    const float* w_k = (const float*)d_in[6];
    const float* b_k = (const float*)d_in[7];
    const float* w_v = (const float*)d_in[8];
    const float* b_v = (const float*)d_in[9];
    const float* w_o = (const float*)d_in[10];
    const float* b_o = (const float*)d_in[11];
    float* out = (float*)d_out;

    cudaFuncSetAttribute(flash_attn_mma, cudaFuncAttributeMaxDynamicSharedMemorySize, ATT_SMEM);

    dim3 gg(DM / 128, T_SEQ / 128);   // (8, 32)
    gemm_mma_proj<<<gg, 256>>>(q, w_q, b_q, 0);
    gemm_mma_proj<<<gg, 256>>>(k, w_k, b_k, 1);
    gemm_mma_proj<<<gg, 256>>>(v, w_v, b_v, 2);
    flash_attn_mma<<<dim3(T_SEQ / 64, NH), 128, ATT_SMEM>>>();
    gemm_mma_out<<<gg, 256>>>(w_o, b_o, out);
}

// round 14
// speedup vs baseline: 1.0058x; 1.0057x over previous
#include <cuda_runtime.h>
#include <cuda_bf16.h>
#include <cstdint>

#define T_SEQ 4096
#define DM    1024
#define NH    16
#define HD    64

// Scratch (allocation-free: __device__ globals)
__device__ __nv_bfloat16 g_qhi[NH * T_SEQ * HD];
__device__ __nv_bfloat16 g_qlo[NH * T_SEQ * HD];
__device__ __nv_bfloat16 g_khi[NH * T_SEQ * HD];
__device__ __nv_bfloat16 g_klo[NH * T_SEQ * HD];
__device__ __nv_bfloat16 g_vhi[NH * T_SEQ * HD];
__device__ __nv_bfloat16 g_vlo[NH * T_SEQ * HD];
__device__ float g_ao[T_SEQ * DM];        // attention output, [T][D]

// ===========================================================================
// Helpers
// ===========================================================================
__device__ __forceinline__ uint32_t smem_to_u32(const void* p) {
    uint32_t a;
    asm("{ .reg .u64 t; cvta.to.shared.u64 t, %1; cvt.u32.u64 %0, t; }"
        : "=r"(a) : "l"(p));
    return a;
}

__device__ __forceinline__ void ldmatrix_x4(uint32_t* r, uint32_t addr) {
    asm volatile("ldmatrix.sync.aligned.m8n8.x4.shared.b16 {%0,%1,%2,%3}, [%4];"
                 : "=r"(r[0]), "=r"(r[1]), "=r"(r[2]), "=r"(r[3]) : "r"(addr));
}

__device__ __forceinline__ void ldmatrix_x4_trans(uint32_t* r, uint32_t addr) {
    asm volatile("ldmatrix.sync.aligned.m8n8.x4.trans.shared.b16 {%0,%1,%2,%3}, [%4];"
                 : "=r"(r[0]), "=r"(r[1]), "=r"(r[2]), "=r"(r[3]) : "r"(addr));
}

__device__ __forceinline__ void mma16816(float* c, const uint32_t* a,
                                         uint32_t b0, uint32_t b1) {
    asm volatile(
        "mma.sync.aligned.m16n8k16.row.col.f32.bf16.bf16.f32 "
        "{%0,%1,%2,%3}, {%4,%5,%6,%7}, {%8,%9}, {%0,%1,%2,%3};"
        : "+f"(c[0]), "+f"(c[1]), "+f"(c[2]), "+f"(c[3])
        : "r"(a[0]), "r"(a[1]), "r"(a[2]), "r"(a[3]), "r"(b0), "r"(b1));
}

__device__ __forceinline__ void cp_async16(uint32_t saddr, const void* gptr) {
    asm volatile("cp.async.cg.shared.global [%0], [%1], 16;"
                 :: "r"(saddr), "l"(gptr) : "memory");
}
#define CP_COMMIT() asm volatile("cp.async.commit_group;" ::: "memory")
#define CP_WAIT(n)  asm volatile("cp.async.wait_group %0;" :: "n"(n) : "memory")

__device__ __forceinline__ uint32_t packbf2(float x, float y) {
    __nv_bfloat162 h = __floats2bfloat162_rn(x, y);
    return *(uint32_t*)&h;
}

// (x, y) -> hi bf16x2 and residual-lo bf16x2
__device__ __forceinline__ void split2(float x, float y, uint32_t& h, uint32_t& l) {
    __nv_bfloat162 H = __floats2bfloat162_rn(x, y);
    __nv_bfloat162 L = __floats2bfloat162_rn(x - __bfloat162float(H.x),
                                             y - __bfloat162float(H.y));
    h = *(uint32_t*)&H; l = *(uint32_t*)&L;
}

__device__ __forceinline__ void split4(float4 v, uint32_t& h0, uint32_t& h1,
                                       uint32_t& l0, uint32_t& l1) {
    split2(v.x, v.y, h0, l0);
    split2(v.z, v.w, h1, l1);
}

__device__ __forceinline__ void sts2(uint32_t addr, uint32_t a, uint32_t b) {
    asm volatile("st.shared.v2.b32 [%0], {%1,%2};" :: "r"(addr), "r"(a), "r"(b) : "memory");
}

// ===========================================================================
// HMMA GEMM: C[M, N=1024] = X[M, K=1024] @ W[N, K]^T + bias[N]  (R6 mainloop)
// CTA 128x128, 8 warps (4m x 2n), warp tile 32x64, K chunk 32, stride 80 B.
// MODE 0: epilogue splits C into bf16 hi/lo, scattered head-major [h][t][64]
// MODE 1: plain fp32 row-major [m][n]
// ===========================================================================
template <int MODE>
__device__ __forceinline__ void gemm_mma_body(const float* __restrict__ X,
                                              const float* __restrict__ W,
                                              const float* __restrict__ bias,
                                              float* __restrict__ outf,
                                              __nv_bfloat16* __restrict__ ohi,
                                              __nv_bfloat16* __restrict__ olo) {
    __shared__ __nv_bfloat16 sAhi[128 * 40];
    __shared__ __nv_bfloat16 sAlo[128 * 40];
    __shared__ __nv_bfloat16 sBhi[128 * 40];
    __shared__ __nv_bfloat16 sBlo[128 * 40];

    const int tid = threadIdx.x;
    const int w = tid >> 5, lane = tid & 31;
    const int wm = w & 3, wn = w >> 2;
    const int bm = blockIdx.y * 128, bn = blockIdx.x * 128;

    const uint32_t uAhi = smem_to_u32(sAhi), uAlo = smem_to_u32(sAlo);
    const uint32_t uBhi = smem_to_u32(sBhi), uBlo = smem_to_u32(sBlo);

    const uint32_t mrow = lane & 15;
    const uint32_t mkb = (lane >> 4) * 16;

    const int grow = tid >> 3;
    const int gc4 = tid & 7;
    const float* Xp = X + (size_t)(bm + grow) * DM + gc4 * 4;
    const float* Wp = W + (size_t)(bn + grow) * DM + gc4 * 4;

    float c[2][8][4] = {};

    for (int k0 = 0; k0 < DM; k0 += 32) {
        float4 av[4], bv[4];
#pragma unroll
        for (int i = 0; i < 4; i++) {
            av[i] = *(const float4*)(Xp + k0 + (size_t)i * 32 * DM);
            bv[i] = *(const float4*)(Wp + k0 + (size_t)i * 32 * DM);
        }
        __syncthreads();
#pragma unroll
        for (int i = 0; i < 4; i++) {
            uint32_t byte = (uint32_t)(grow + 32 * i) * 80u + (uint32_t)gc4 * 8u;
            uint32_t h0, h1, l0, l1;
            split4(av[i], h0, h1, l0, l1);
            sts2(uAhi + byte, h0, h1);
            sts2(uAlo + byte, l0, l1);
            split4(bv[i], h0, h1, l0, l1);
            sts2(uBhi + byte, h0, h1);
            sts2(uBlo + byte, l0, l1);
        }
        __syncthreads();

#pragma unroll
        for (int ks = 0; ks < 2; ks++) {
            const uint32_t kbyte = (uint32_t)ks * 32u + mkb;
            uint32_t ah[2][4], al[2][4];
#pragma unroll
            for (int mt = 0; mt < 2; mt++) {
                uint32_t off = (uint32_t)(wm * 32 + mt * 16 + mrow) * 80u + kbyte;
                ldmatrix_x4(ah[mt], uAhi + off);
                ldmatrix_x4(al[mt], uAlo + off);
            }
#pragma unroll
            for (int np = 0; np < 4; np++) {
                uint32_t bh[4], bl[4];
                uint32_t off = (uint32_t)(wn * 64 + np * 16 + mrow) * 80u + kbyte;
                ldmatrix_x4(bh, uBhi + off);
                ldmatrix_x4(bl, uBlo + off);
#pragma unroll
                for (int mt = 0; mt < 2; mt++) {
                    float* c0 = c[mt][2 * np + 0];
                    float* c1 = c[mt][2 * np + 1];
                    mma16816(c0, ah[mt], bh[0], bh[2]);
                    mma16816(c1, ah[mt], bh[1], bh[3]);
                    mma16816(c0, ah[mt], bl[0], bl[2]);
                    mma16816(c1, ah[mt], bl[1], bl[3]);
                    mma16816(c0, al[mt], bh[0], bh[2]);
                    mma16816(c1, al[mt], bh[1], bh[3]);
                }
            }
        }
    }

    const int g = lane >> 2, tg = lane & 3;
#pragma unroll
    for (int mt = 0; mt < 2; mt++) {
#pragma unroll
        for (int j = 0; j < 8; j++) {
            int col = bn + wn * 64 + j * 8 + tg * 2;
            float bb0 = __ldg(bias + col), bb1 = __ldg(bias + col + 1);
            int r0 = bm + wm * 32 + mt * 16 + g;
            float cx0 = c[mt][j][0] + bb0, cy0 = c[mt][j][1] + bb1;
            float cx1 = c[mt][j][2] + bb0, cy1 = c[mt][j][3] + bb1;
            if (MODE == 0) {
                size_t basep = ((size_t)((col >> 6) * T_SEQ)) * HD + (col & 63);
                size_t i0 = basep + (size_t)r0 * HD;
                size_t i1 = basep + (size_t)(r0 + 8) * HD;
                uint32_t h, l;
                split2(cx0, cy0, h, l);
                *(uint32_t*)(ohi + i0) = h; *(uint32_t*)(olo + i0) = l;
                split2(cx1, cy1, h, l);
                *(uint32_t*)(ohi + i1) = h; *(uint32_t*)(olo + i1) = l;
            } else {
                *(float2*)(outf + (size_t)r0 * DM + col) = make_float2(cx0, cy0);
                *(float2*)(outf + (size_t)(r0 + 8) * DM + col) = make_float2(cx1, cy1);
            }
        }
    }
}

__global__ void __launch_bounds__(256, 2) gemm_mma_proj(const float* __restrict__ X,
                                                        const float* __restrict__ W,
                                                        const float* __restrict__ bias,
                                                        int which) {
    __nv_bfloat16* ohi = (which == 0) ? g_qhi : (which == 1) ? g_khi : g_vhi;
    __nv_bfloat16* olo = (which == 0) ? g_qlo : (which == 1) ? g_klo : g_vlo;
    gemm_mma_body<0>(X, W, bias, nullptr, ohi, olo);
}

__global__ void __launch_bounds__(256, 2) gemm_mma_out(const float* __restrict__ W,
                                                       const float* __restrict__ bias,
                                                       float* __restrict__ out) {
    gemm_mma_body<1>(g_ao, W, bias, out, nullptr, nullptr);
}

// ===========================================================================
// HMMA flash attention (causal). Block = (64-query tile, head), 4 warps.
// R9: K/V/Q arrive PRE-SPLIT as bf16 hi/lo; cp.async loads them straight into
// ldmatrix-ready smem (144 B row stride). No conversion in the loop. Double-
// buffered: 2 stages x (Khi|Klo|Vhi|Vlo) x 9216 B = 72 KB -> 3 CTAs/SM.
// ===========================================================================
#define AST   72                      // bf16 row stride (144 B)
#define AREG  (64 * AST * 2)          // one array region: 9216 B
#define ASTAGE (4 * AREG)             // one stage: 36864 B
#define ATT_SMEM (2 * ASTAGE)         // 73728 B

__global__ void __launch_bounds__(128) flash_attn_mma() {
    extern __shared__ char dsm[];
    const uint32_t base = smem_to_u32(dsm);

    const int tid = threadIdx.x;
    const int w = tid >> 5, lane = tid & 31;
    const int g = lane >> 2, tg = lane & 3;
    const uint32_t mrow = lane & 15;
    const uint32_t mkb = (lane >> 4) * 16;
    const int qt = (int)gridDim.x - 1 - (int)blockIdx.x;   // big tiles first
    const int h = blockIdx.y;
    const int q0 = qt * 64;

    // cp.async mapping: per array 512 16B-chunks; 128 threads x 4 chunks
    // chunk c = tid + 128*i -> row = c>>3, ch = c&7
    const __nv_bfloat16* Khi0 = g_khi + (size_t)h * T_SEQ * HD;
    const __nv_bfloat16* Klo0 = g_klo + (size_t)h * T_SEQ * HD;
    const __nv_bfloat16* Vhi0 = g_vhi + (size_t)h * T_SEQ * HD;
    const __nv_bfloat16* Vlo0 = g_vlo + (size_t)h * T_SEQ * HD;

    // ---- prologue: Q (into stage1 K region) + key tile 0 (stage0), 1 group
    {
        const __nv_bfloat16* Qhi = g_qhi + ((size_t)h * T_SEQ + q0) * HD;
        const __nv_bfloat16* Qlo = g_qlo + ((size_t)h * T_SEQ + q0) * HD;
#pragma unroll
        for (int i = 0; i < 4; i++) {
            int c = tid + 128 * i;
            int row = c >> 3, ch = c & 7;
            uint32_t dst = (uint32_t)row * (AST * 2u) + (uint32_t)ch * 16u;
            size_t src = (size_t)row * HD + ch * 8;
            cp_async16(base + ASTAGE + dst,            Qhi + src);   // stage1 Khi
            cp_async16(base + ASTAGE + AREG + dst,     Qlo + src);   // stage1 Klo
            cp_async16(base + dst,                     Khi0 + src);  // stage0
            cp_async16(base + AREG + dst,              Klo0 + src);
            cp_async16(base + 2 * AREG + dst,          Vhi0 + src);
            cp_async16(base + 3 * AREG + dst,          Vlo0 + src);
        }
        CP_COMMIT();
        CP_WAIT(0);
    }
    __syncthreads();

    // ---- hoist Q fragments from stage1 K region ----
    uint32_t qh[4][4], ql[4][4];
#pragma unroll
    for (int kc = 0; kc < 4; kc++) {
        uint32_t off = (uint32_t)(w * 16 + mrow) * (AST * 2u) + (uint32_t)kc * 32u + mkb;
        ldmatrix_x4(qh[kc], base + ASTAGE + off);
        ldmatrix_x4(ql[kc], base + ASTAGE + AREG + off);
    }

    float O[8][4] = {};
    float m0 = -1e30f, m1 = -1e30f, l0s = 0.f, l1s = 0.f;

    for (int kt = 0; kt <= qt; kt++) {
        __syncthreads();   // prior compute (or Q hoist) done before overwrite
        if (kt < qt) {
            const uint32_t sb = (uint32_t)((kt + 1) & 1) * ASTAGE;
            const size_t t0 = (size_t)(kt + 1) * 64 * HD;
#pragma unroll
            for (int i = 0; i < 4; i++) {
                int c = tid + 128 * i;
                int row = c >> 3, ch = c & 7;
                uint32_t dst = sb + (uint32_t)row * (AST * 2u) + (uint32_t)ch * 16u;
                size_t src = t0 + (size_t)row * HD + ch * 8;
                cp_async16(base + dst,            Khi0 + src);
                cp_async16(base + AREG + dst,     Klo0 + src);
                cp_async16(base + 2 * AREG + dst, Vhi0 + src);
                cp_async16(base + 3 * AREG + dst, Vlo0 + src);
            }
            CP_COMMIT();
            CP_WAIT(1);
        } else {
            CP_WAIT(0);
        }
        __syncthreads();

        const uint32_t uKhi = base + (uint32_t)(kt & 1) * ASTAGE;
        const uint32_t uKlo = uKhi + AREG;
        const uint32_t uVhi = uKhi + 2 * AREG;
        const uint32_t uVlo = uKhi + 3 * AREG;

        // ---- S = Q @ K^T (c[j] = 8-col key tile j) ----
        float c[8][4] = {};
#pragma unroll
        for (int kc = 0; kc < 4; kc++) {
#pragma unroll
            for (int np = 0; np < 4; np++) {
                uint32_t kh[4], kl[4];
                uint32_t off = (uint32_t)(np * 16 + mrow) * (AST * 2u) + (uint32_t)kc * 32u + mkb;
                ldmatrix_x4(kh, uKhi + off);
                ldmatrix_x4(kl, uKlo + off);
                float* c0 = c[2 * np + 0];
                float* c1 = c[2 * np + 1];
                mma16816(c0, qh[kc], kh[0], kh[2]);
                mma16816(c1, qh[kc], kh[1], kh[3]);
                mma16816(c0, qh[kc], kl[0], kl[2]);
                mma16816(c1, qh[kc], kl[1], kl[3]);
                mma16816(c0, ql[kc], kh[0], kh[2]);
                mma16816(c1, ql[kc], kh[1], kh[3]);
            }
        }

        // ---- scale + causal mask (diag tile only) ----
        const float scale = 0.125f;
        if (kt == qt) {
            const int r0 = 16 * w + g, r1 = r0 + 8;
#pragma unroll
            for (int j = 0; j < 8; j++) {
                int col = 8 * j + 2 * tg;
                c[j][0] = (col     <= r0) ? c[j][0] * scale : -1e30f;
                c[j][1] = (col + 1 <= r0) ? c[j][1] * scale : -1e30f;
                c[j][2] = (col     <= r1) ? c[j][2] * scale : -1e30f;
                c[j][3] = (col + 1 <= r1) ? c[j][3] * scale : -1e30f;
            }
        } else {
#pragma unroll
            for (int j = 0; j < 8; j++)
#pragma unroll
                for (int q = 0; q < 4; q++) c[j][q] *= scale;
        }

        // ---- online softmax (rows g and g+8; reduce over 4-lane group) ----
        float rm0 = -1e30f, rm1 = -1e30f;
#pragma unroll
        for (int j = 0; j < 8; j++) {
            rm0 = fmaxf(rm0, fmaxf(c[j][0], c[j][1]));
            rm1 = fmaxf(rm1, fmaxf(c[j][2], c[j][3]));
        }
        rm0 = fmaxf(rm0, __shfl_xor_sync(0xffffffffu, rm0, 1));
        rm0 = fmaxf(rm0, __shfl_xor_sync(0xffffffffu, rm0, 2));
        rm1 = fmaxf(rm1, __shfl_xor_sync(0xffffffffu, rm1, 1));
        rm1 = fmaxf(rm1, __shfl_xor_sync(0xffffffffu, rm1, 2));

        float mn0 = fmaxf(m0, rm0), mn1 = fmaxf(m1, rm1);
        float a0 = __expf(m0 - mn0), a1 = __expf(m1 - mn1);
        m0 = mn0; m1 = mn1;

        float rs0 = 0.f, rs1 = 0.f;
#pragma unroll
        for (int j = 0; j < 8; j++) {
            c[j][0] = __expf(c[j][0] - mn0);
            c[j][1] = __expf(c[j][1] - mn0);
            c[j][2] = __expf(c[j][2] - mn1);
            c[j][3] = __expf(c[j][3] - mn1);
            rs0 += c[j][0] + c[j][1];
            rs1 += c[j][2] + c[j][3];
        }
        rs0 += __shfl_xor_sync(0xffffffffu, rs0, 1);
        rs0 += __shfl_xor_sync(0xffffffffu, rs0, 2);
        rs1 += __shfl_xor_sync(0xffffffffu, rs1, 1);
        rs1 += __shfl_xor_sync(0xffffffffu, rs1, 2);
        l0s = l0s * a0 + rs0;
        l1s = l1s * a1 + rs1;
#pragma unroll
        for (int j = 0; j < 8; j++) {
            O[j][0] *= a0; O[j][1] *= a0;
            O[j][2] *= a1; O[j][3] *= a1;
        }

        // ---- O += P @ V  (P fragments straight from c; V via ldmatrix.trans)
#pragma unroll
        for (int kc = 0; kc < 4; kc++) {
            const int j0 = 2 * kc, j1 = 2 * kc + 1;
            uint32_t ph[4], pl[4];
            {
                uint32_t hh, ll;
                split2(c[j0][0], c[j0][1], hh, ll); ph[0] = hh; pl[0] = ll;
                split2(c[j0][2], c[j0][3], hh, ll); ph[1] = hh; pl[1] = ll;
                split2(c[j1][0], c[j1][1], hh, ll); ph[2] = hh; pl[2] = ll;
                split2(c[j1][2], c[j1][3], hh, ll); ph[3] = hh; pl[3] = ll;
            }
#pragma unroll
            for (int dt = 0; dt < 4; dt++) {
                uint32_t vh[4], vl[4];
                uint32_t off = (uint32_t)(kc * 16 + mrow) * (AST * 2u) + (uint32_t)dt * 32u + mkb;
                ldmatrix_x4_trans(vh, uVhi + off);
                ldmatrix_x4_trans(vl, uVlo + off);
                float* o0 = O[2 * dt + 0];
                float* o1 = O[2 * dt + 1];
                mma16816(o0, ph, vh[0], vh[1]);
                mma16816(o1, ph, vh[2], vh[3]);
                mma16816(o0, ph, vl[0], vl[1]);
                mma16816(o1, ph, vl[2], vl[3]);
                mma16816(o0, pl, vh[0], vh[1]);
                mma16816(o1, pl, vh[2], vh[3]);
            }
        }
    }

    // ---- epilogue: O / l -> g_ao[t][h*64 + d] ----
    const float inv0 = 1.0f / l0s, inv1 = 1.0f / l1s;
    const int r0 = q0 + 16 * w + g, r1 = r0 + 8;
#pragma unroll
    for (int j = 0; j < 8; j++) {
        int d = 8 * j + 2 * tg;
        float2 v0 = {O[j][0] * inv0, O[j][1] * inv0};
        float2 v1 = {O[j][2] * inv1, O[j][3] * inv1};
        *(float2*)(g_ao + (size_t)r0 * DM + h * HD + d) = v0;
        *(float2*)(g_ao + (size_t)r1 * DM + h * HD + d) = v1;
    }
}

// ---------------------------------------------------------------------------
extern "C" void kernel_launch(void* const* d_in, const int* in_sizes, int n_in,
                              void* d_out, int out_size) {
    const float* q   = (const float*)d_in[0];
    const float* k   = (const float*)d_in[1];
    const float* v   = (const float*)d_in[2];
    // d_in[3] = causal mask (bool) — implied by causal structure, unused
    const float* w_q = (const float*)d_in[4];
    const float* b_q = (const float*)d_in[5];
    const float* w_k = (const float*)d_in[6];
    const float* b_k = (const float*)d_in[7];
    const float* w_v = (const float*)d_in[8];
    const float* b_v = (const float*)d_in[9];
    const float* w_o = (const float*)d_in[10];
    const float* b_o = (const float*)d_in[11];
    float* out = (float*)d_out;

    cudaFuncSetAttribute(flash_attn_mma, cudaFuncAttributeMaxDynamicSharedMemorySize, ATT_SMEM);

    dim3 gg(DM / 128, T_SEQ / 128);   // (8, 32)
    gemm_mma_proj<<<gg, 256>>>(q, w_q, b_q, 0);
    gemm_mma_proj<<<gg, 256>>>(k, w_k, b_k, 1);
    gemm_mma_proj<<<gg, 256>>>(v, w_v, b_v, 2);
    flash_attn_mma<<<dim3(T_SEQ / 64, NH), 128, ATT_SMEM>>>();
    gemm_mma_out<<<gg, 256>>>(w_o, b_o, out);
}